// round 6
// baseline (speedup 1.0000x reference)
#include <cuda_runtime.h>
#include <math.h>

#define DIMD   512
#define HEADS  8
#define HD     64
#define MLPD   2048
#define BATCH  2
#define SEQ    4096
#define BN_TOK 8192   // BATCH*SEQ

// ---------------- scratch (static device arrays; no allocation) -------------
__device__ float g_h  [(size_t)BN_TOK * DIMD];
__device__ float g_q  [(size_t)BN_TOK * DIMD];
__device__ float g_k  [(size_t)BN_TOK * DIMD];
__device__ float g_v  [(size_t)BN_TOK * DIMD];
__device__ float g_att[(size_t)BN_TOK * DIMD];
__device__ float g_xm [(size_t)BN_TOK * DIMD];
__device__ float g_ff [(size_t)BN_TOK * MLPD];
__device__ float g_S  [(size_t)BATCH * HEADS * SEQ * SEQ];   // 1 GB scores

__device__ __forceinline__ float gelu_exact(float x) {
    return 0.5f * x * (1.0f + erff(x * 0.70710678118654752440f));
}

// ---------------- LayerNorm: one block (128 thr) per row of 512 -------------
__global__ void ln_kernel(const float* __restrict__ x, const float* __restrict__ g,
                          const float* __restrict__ be, float* __restrict__ out) {
    int row = blockIdx.x;
    int t = threadIdx.x;                       // 0..127
    const float4* xr = (const float4*)(x + (size_t)row * DIMD);
    float4 v = xr[t];
    float s  = v.x + v.y + v.z + v.w;
    float sq = v.x * v.x + v.y * v.y + v.z * v.z + v.w * v.w;
    #pragma unroll
    for (int o = 16; o > 0; o >>= 1) {
        s  += __shfl_xor_sync(0xffffffffu, s,  o);
        sq += __shfl_xor_sync(0xffffffffu, sq, o);
    }
    __shared__ float rs_[4], rq_[4];
    int lane = t & 31, w = t >> 5;
    if (lane == 0) { rs_[w] = s; rq_[w] = sq; }
    __syncthreads();
    s  = rs_[0] + rs_[1] + rs_[2] + rs_[3];
    sq = rq_[0] + rq_[1] + rq_[2] + rq_[3];
    float mu  = s * (1.0f / DIMD);
    float var = sq * (1.0f / DIMD) - mu * mu;
    float rstd = rsqrtf(var + 1e-5f);
    float4 gg = ((const float4*)g)[t];
    float4 bb = ((const float4*)be)[t];
    float4 o4;
    o4.x = (v.x - mu) * rstd * gg.x + bb.x;
    o4.y = (v.y - mu) * rstd * gg.y + bb.y;
    o4.z = (v.z - mu) * rstd * gg.z + bb.z;
    o4.w = (v.w - mu) * rstd * gg.w + bb.w;
    ((float4*)(out + (size_t)row * DIMD))[t] = o4;
}

// ---------------- Generic NN GEMM: C[M,N] = A[M,K] @ B[K,N] (+epilogue) -----
// BM=128, BN=128, BK=16, 256 threads, 8x8 per-thread tile.
// EPI: 0 = none, 1 = +bias, 2 = +bias then GELU, 3 = +bias +residual
template <int EPI>
__global__ void gemm_nn(const float* __restrict__ A, const float* __restrict__ Bm,
                        const float* __restrict__ bias, const float* __restrict__ R,
                        float* __restrict__ C, int M, int Ncols, int K) {
    __shared__ float As[16][132];
    __shared__ float Bs[16][128];
    int tid = threadIdx.x;
    int tx = tid & 15, ty = tid >> 4;
    int rowTile = blockIdx.y * 128, colTile = blockIdx.x * 128;
    int lr  = tid >> 2;            // 0..63
    int lc4 = (tid & 3) * 4;       // 0,4,8,12
    int br  = tid >> 5;            // 0..7
    int bc4 = (tid & 31) * 4;      // 0..124
    float acc[8][8] = {};
    for (int k0 = 0; k0 < K; k0 += 16) {
        float4 a0 = *(const float4*)(A + (size_t)(rowTile + lr)      * K + k0 + lc4);
        float4 a1 = *(const float4*)(A + (size_t)(rowTile + lr + 64) * K + k0 + lc4);
        As[lc4 + 0][lr] = a0.x;  As[lc4 + 1][lr] = a0.y;
        As[lc4 + 2][lr] = a0.z;  As[lc4 + 3][lr] = a0.w;
        As[lc4 + 0][lr + 64] = a1.x;  As[lc4 + 1][lr + 64] = a1.y;
        As[lc4 + 2][lr + 64] = a1.z;  As[lc4 + 3][lr + 64] = a1.w;
        float4 b0 = *(const float4*)(Bm + (size_t)(k0 + br)     * Ncols + colTile + bc4);
        float4 b1 = *(const float4*)(Bm + (size_t)(k0 + br + 8) * Ncols + colTile + bc4);
        *(float4*)&Bs[br][bc4]     = b0;
        *(float4*)&Bs[br + 8][bc4] = b1;
        __syncthreads();
        #pragma unroll
        for (int kk = 0; kk < 16; kk++) {
            float ra[8], rb[8];
            *(float4*)&ra[0] = *(float4*)&As[kk][ty * 8];
            *(float4*)&ra[4] = *(float4*)&As[kk][ty * 8 + 4];
            *(float4*)&rb[0] = *(float4*)&Bs[kk][tx * 8];
            *(float4*)&rb[4] = *(float4*)&Bs[kk][tx * 8 + 4];
            #pragma unroll
            for (int i = 0; i < 8; i++)
                #pragma unroll
                for (int j = 0; j < 8; j++)
                    acc[i][j] = fmaf(ra[i], rb[j], acc[i][j]);
        }
        __syncthreads();
    }
    int col0 = colTile + tx * 8;
    float4 bia0, bia1;
    if (EPI >= 1) {
        bia0 = *(const float4*)&bias[col0];
        bia1 = *(const float4*)&bias[col0 + 4];
    }
    #pragma unroll
    for (int i = 0; i < 8; i++) {
        int row = rowTile + ty * 8 + i;
        float4 o0 = make_float4(acc[i][0], acc[i][1], acc[i][2], acc[i][3]);
        float4 o1 = make_float4(acc[i][4], acc[i][5], acc[i][6], acc[i][7]);
        if (EPI >= 1) {
            o0.x += bia0.x; o0.y += bia0.y; o0.z += bia0.z; o0.w += bia0.w;
            o1.x += bia1.x; o1.y += bia1.y; o1.z += bia1.z; o1.w += bia1.w;
        }
        if (EPI == 2) {
            o0.x = gelu_exact(o0.x); o0.y = gelu_exact(o0.y);
            o0.z = gelu_exact(o0.z); o0.w = gelu_exact(o0.w);
            o1.x = gelu_exact(o1.x); o1.y = gelu_exact(o1.y);
            o1.z = gelu_exact(o1.z); o1.w = gelu_exact(o1.w);
        }
        if (EPI == 3) {
            float4 r0 = *(const float4*)(R + (size_t)row * Ncols + col0);
            float4 r1 = *(const float4*)(R + (size_t)row * Ncols + col0 + 4);
            o0.x += r0.x; o0.y += r0.y; o0.z += r0.z; o0.w += r0.w;
            o1.x += r1.x; o1.y += r1.y; o1.z += r1.z; o1.w += r1.w;
        }
        *(float4*)(C + (size_t)row * Ncols + col0)     = o0;
        *(float4*)(C + (size_t)row * Ncols + col0 + 4) = o1;
    }
}

// ---------------- Attention scores: S = (Q @ K^T) / 8, per (b,h) ------------
// NT GEMM, M=N=4096, K=64. grid (32, 32, 16), 256 threads.
__global__ void score_kernel(const float* __restrict__ q, const float* __restrict__ k,
                             float* __restrict__ S) {
    int z = blockIdx.z, b = z >> 3, hh = z & 7;
    const float* A  = q + (size_t)b * SEQ * DIMD + hh * HD;
    const float* Bp = k + (size_t)b * SEQ * DIMD + hh * HD;
    float* C = S + (size_t)z * SEQ * SEQ;
    __shared__ float As[16][132];
    __shared__ float Bs[16][132];
    int tid = threadIdx.x;
    int tx = tid & 15, ty = tid >> 4;
    int rowTile = blockIdx.y * 128, colTile = blockIdx.x * 128;
    int lr = tid >> 2, lc4 = (tid & 3) * 4;
    float acc[8][8] = {};
    for (int k0 = 0; k0 < HD; k0 += 16) {
        float4 a0 = *(const float4*)(A + (size_t)(rowTile + lr)      * DIMD + k0 + lc4);
        float4 a1 = *(const float4*)(A + (size_t)(rowTile + lr + 64) * DIMD + k0 + lc4);
        As[lc4 + 0][lr] = a0.x;  As[lc4 + 1][lr] = a0.y;
        As[lc4 + 2][lr] = a0.z;  As[lc4 + 3][lr] = a0.w;
        As[lc4 + 0][lr + 64] = a1.x;  As[lc4 + 1][lr + 64] = a1.y;
        As[lc4 + 2][lr + 64] = a1.z;  As[lc4 + 3][lr + 64] = a1.w;
        float4 b0 = *(const float4*)(Bp + (size_t)(colTile + lr)      * DIMD + k0 + lc4);
        float4 b1 = *(const float4*)(Bp + (size_t)(colTile + lr + 64) * DIMD + k0 + lc4);
        Bs[lc4 + 0][lr] = b0.x;  Bs[lc4 + 1][lr] = b0.y;
        Bs[lc4 + 2][lr] = b0.z;  Bs[lc4 + 3][lr] = b0.w;
        Bs[lc4 + 0][lr + 64] = b1.x;  Bs[lc4 + 1][lr + 64] = b1.y;
        Bs[lc4 + 2][lr + 64] = b1.z;  Bs[lc4 + 3][lr + 64] = b1.w;
        __syncthreads();
        #pragma unroll
        for (int kk = 0; kk < 16; kk++) {
            float ra[8], rb[8];
            *(float4*)&ra[0] = *(float4*)&As[kk][ty * 8];
            *(float4*)&ra[4] = *(float4*)&As[kk][ty * 8 + 4];
            *(float4*)&rb[0] = *(float4*)&Bs[kk][tx * 8];
            *(float4*)&rb[4] = *(float4*)&Bs[kk][tx * 8 + 4];
            #pragma unroll
            for (int i = 0; i < 8; i++)
                #pragma unroll
                for (int j = 0; j < 8; j++)
                    acc[i][j] = fmaf(ra[i], rb[j], acc[i][j]);
        }
        __syncthreads();
    }
    const float scale = 0.125f;  // 1/sqrt(64)
    int col0 = colTile + tx * 8;
    #pragma unroll
    for (int i = 0; i < 8; i++) {
        int row = rowTile + ty * 8 + i;
        float4 o0 = make_float4(acc[i][0]*scale, acc[i][1]*scale, acc[i][2]*scale, acc[i][3]*scale);
        float4 o1 = make_float4(acc[i][4]*scale, acc[i][5]*scale, acc[i][6]*scale, acc[i][7]*scale);
        *(float4*)(C + (size_t)row * SEQ + col0)     = o0;
        *(float4*)(C + (size_t)row * SEQ + col0 + 4) = o1;
    }
}

// ---------------- Row softmax over 4096, in-place, row in registers ---------
__global__ void softmax_kernel(float* __restrict__ S) {
    size_t base = (size_t)blockIdx.x * SEQ;
    float4* p = (float4*)(S + base);
    int t = threadIdx.x;               // 256
    float4 v[4];
    #pragma unroll
    for (int i = 0; i < 4; i++) v[i] = p[i * 256 + t];
    float m = v[0].x;
    #pragma unroll
    for (int i = 0; i < 4; i++) {
        m = fmaxf(m, fmaxf(fmaxf(v[i].x, v[i].y), fmaxf(v[i].z, v[i].w)));
    }
    #pragma unroll
    for (int o = 16; o > 0; o >>= 1) m = fmaxf(m, __shfl_xor_sync(0xffffffffu, m, o));
    __shared__ float sm[8], ss[8];
    int lane = t & 31, w = t >> 5;
    if (lane == 0) sm[w] = m;
    __syncthreads();
    float mm = sm[0];
    #pragma unroll
    for (int i = 1; i < 8; i++) mm = fmaxf(mm, sm[i]);
    float s = 0.0f;
    #pragma unroll
    for (int i = 0; i < 4; i++) {
        v[i].x = __expf(v[i].x - mm); v[i].y = __expf(v[i].y - mm);
        v[i].z = __expf(v[i].z - mm); v[i].w = __expf(v[i].w - mm);
        s += v[i].x + v[i].y + v[i].z + v[i].w;
    }
    #pragma unroll
    for (int o = 16; o > 0; o >>= 1) s += __shfl_xor_sync(0xffffffffu, s, o);
    if (lane == 0) ss[w] = s;
    __syncthreads();
    float tot = ss[0] + ss[1] + ss[2] + ss[3] + ss[4] + ss[5] + ss[6] + ss[7];
    float r = 1.0f / tot;
    #pragma unroll
    for (int i = 0; i < 4; i++) {
        v[i].x *= r; v[i].y *= r; v[i].z *= r; v[i].w *= r;
        p[i * 256 + t] = v[i];
    }
}

// ---------------- PV: att_head = P @ V, per (b,h). M=4096,N=64,K=4096 -------
// grid (32, 16), 256 threads, BM=128, BN=64, 8x4 per-thread tile.
__global__ void pv_kernel(const float* __restrict__ S, const float* __restrict__ v,
                          float* __restrict__ att) {
    int z = blockIdx.y, b = z >> 3, hh = z & 7;
    const float* A  = S   + (size_t)z * SEQ * SEQ;
    const float* Bp = v   + (size_t)b * SEQ * DIMD + hh * HD;
    float* C        = att + (size_t)b * SEQ * DIMD + hh * HD;
    __shared__ float As[16][132];
    __shared__ float Bs[16][64];
    int tid = threadIdx.x;
    int tx = tid & 15, ty = tid >> 4;
    int rowTile = blockIdx.x * 128;
    int lr = tid >> 2, lc4 = (tid & 3) * 4;
    int brow = tid >> 4, bc4 = (tid & 15) * 4;
    float acc[8][4] = {};
    for (int k0 = 0; k0 < SEQ; k0 += 16) {
        float4 a0 = *(const float4*)(A + (size_t)(rowTile + lr)      * SEQ + k0 + lc4);
        float4 a1 = *(const float4*)(A + (size_t)(rowTile + lr + 64) * SEQ + k0 + lc4);
        As[lc4 + 0][lr] = a0.x;  As[lc4 + 1][lr] = a0.y;
        As[lc4 + 2][lr] = a0.z;  As[lc4 + 3][lr] = a0.w;
        As[lc4 + 0][lr + 64] = a1.x;  As[lc4 + 1][lr + 64] = a1.y;
        As[lc4 + 2][lr + 64] = a1.z;  As[lc4 + 3][lr + 64] = a1.w;
        *(float4*)&Bs[brow][bc4] =
            *(const float4*)(Bp + (size_t)(k0 + brow) * DIMD + bc4);
        __syncthreads();
        #pragma unroll
        for (int kk = 0; kk < 16; kk++) {
            float ra[8], rb[4];
            *(float4*)&ra[0] = *(float4*)&As[kk][ty * 8];
            *(float4*)&ra[4] = *(float4*)&As[kk][ty * 8 + 4];
            *(float4*)&rb[0] = *(float4*)&Bs[kk][tx * 4];
            #pragma unroll
            for (int i = 0; i < 8; i++)
                #pragma unroll
                for (int j = 0; j < 4; j++)
                    acc[i][j] = fmaf(ra[i], rb[j], acc[i][j]);
        }
        __syncthreads();
    }
    #pragma unroll
    for (int i = 0; i < 8; i++) {
        int row = rowTile + ty * 8 + i;
        float4 o = make_float4(acc[i][0], acc[i][1], acc[i][2], acc[i][3]);
        *(float4*)(C + (size_t)row * DIMD + tx * 4) = o;
    }
}

// ---------------- launch --------------------------------------------------
extern "C" void kernel_launch(void* const* d_in, const int* in_sizes, int n_in,
                              void* d_out, int out_size) {
    const float* x   = (const float*)d_in[0];
    const float* Wq  = (const float*)d_in[1];
    const float* Wk  = (const float*)d_in[2];
    const float* Wv  = (const float*)d_in[3];
    const float* Wo  = (const float*)d_in[4];
    const float* bo  = (const float*)d_in[5];
    const float* W1  = (const float*)d_in[6];
    const float* b1  = (const float*)d_in[7];
    const float* W2  = (const float*)d_in[8];
    const float* b2  = (const float*)d_in[9];
    const float* g1  = (const float*)d_in[10];
    const float* be1 = (const float*)d_in[11];
    const float* g2  = (const float*)d_in[12];
    const float* be2 = (const float*)d_in[13];
    float* out = (float*)d_out;

    float *h, *q, *k, *v, *att, *xm, *ff, *S;
    cudaGetSymbolAddress((void**)&h,   g_h);
    cudaGetSymbolAddress((void**)&q,   g_q);
    cudaGetSymbolAddress((void**)&k,   g_k);
    cudaGetSymbolAddress((void**)&v,   g_v);
    cudaGetSymbolAddress((void**)&att, g_att);
    cudaGetSymbolAddress((void**)&xm,  g_xm);
    cudaGetSymbolAddress((void**)&ff,  g_ff);
    cudaGetSymbolAddress((void**)&S,   g_S);

    dim3 gProj(DIMD / 128, BN_TOK / 128);       // (4, 64)
    dim3 gMlp(MLPD / 128, BN_TOK / 128);        // (16, 64)

    // 1) h = LN(x; g1, be1)
    ln_kernel<<<BN_TOK, 128>>>(x, g1, be1, h);
    // 2) q, k, v projections
    gemm_nn<0><<<gProj, 256>>>(h, Wq, nullptr, nullptr, q, BN_TOK, DIMD, DIMD);
    gemm_nn<0><<<gProj, 256>>>(h, Wk, nullptr, nullptr, k, BN_TOK, DIMD, DIMD);
    gemm_nn<0><<<gProj, 256>>>(h, Wv, nullptr, nullptr, v, BN_TOK, DIMD, DIMD);
    // 3) S = QK^T / sqrt(hd)  per (b, head)
    score_kernel<<<dim3(SEQ / 128, SEQ / 128, BATCH * HEADS), 256>>>(q, k, S);
    // 4) softmax rows
    softmax_kernel<<<BATCH * HEADS * SEQ, 256>>>(S);
    // 5) att = P @ V  (concat heads)
    pv_kernel<<<dim3(SEQ / 128, BATCH * HEADS), 256>>>(S, v, att);
    // 6) xm = x + att @ Wo + bo
    gemm_nn<3><<<gProj, 256>>>(att, Wo, bo, x, xm, BN_TOK, DIMD, DIMD);
    // 7) h = LN(xm; g2, be2)
    ln_kernel<<<BN_TOK, 128>>>(xm, g2, be2, h);
    // 8) ff = gelu(h @ W1 + b1)
    gemm_nn<2><<<gMlp, 256>>>(h, W1, b1, nullptr, ff, BN_TOK, MLPD, DIMD);
    // 9) out = xm + ff @ W2 + b2
    gemm_nn<3><<<gProj, 256>>>(ff, W2, b2, xm, out, BN_TOK, DIMD, MLPD);
}

// round 7
// speedup vs baseline: 1.1889x; 1.1889x over previous
#include <cuda_runtime.h>
#include <math.h>
#include <stdint.h>

#define DIMD   512
#define HEADS  8
#define HD     64
#define MLPD   2048
#define BATCH  2
#define SEQ    4096
#define BN_TOK 8192   // BATCH*SEQ

// ---------------- scratch (static device arrays; no allocation) -------------
__device__ float g_h  [(size_t)BN_TOK * DIMD];
__device__ float g_q  [(size_t)BN_TOK * DIMD];
__device__ float g_k  [(size_t)BN_TOK * DIMD];
__device__ float g_v  [(size_t)BN_TOK * DIMD];
__device__ float g_att[(size_t)BN_TOK * DIMD];
__device__ float g_xm [(size_t)BN_TOK * DIMD];
__device__ float g_ff [(size_t)BN_TOK * MLPD];
__device__ float g_S  [(size_t)BATCH * HEADS * SEQ * SEQ];   // 1 GB scores

__device__ __forceinline__ float gelu_exact(float x) {
    return 0.5f * x * (1.0f + erff(x * 0.70710678118654752440f));
}

// tf32 helpers ---------------------------------------------------------------
__device__ __forceinline__ void split_tf32(float x, float& hi, float& lo) {
    uint32_t hb;
    asm("cvt.rna.tf32.f32 %0, %1;" : "=r"(hb) : "f"(x));
    hi = __uint_as_float(hb);
    float l = x - hi;
    uint32_t lb;
    asm("cvt.rna.tf32.f32 %0, %1;" : "=r"(lb) : "f"(l));
    lo = __uint_as_float(lb);
}

__device__ __forceinline__ void mma_tf32(float* c, const uint32_t* a, const uint32_t* b) {
    asm volatile(
        "mma.sync.aligned.m16n8k8.row.col.f32.tf32.tf32.f32 "
        "{%0,%1,%2,%3},{%4,%5,%6,%7},{%8,%9},{%0,%1,%2,%3};\n"
        : "+f"(c[0]), "+f"(c[1]), "+f"(c[2]), "+f"(c[3])
        : "r"(a[0]), "r"(a[1]), "r"(a[2]), "r"(a[3]), "r"(b[0]), "r"(b[1]));
}

// ---------------- LayerNorm: one block (128 thr) per row of 512 -------------
__global__ void ln_kernel(const float* __restrict__ x, const float* __restrict__ g,
                          const float* __restrict__ be, float* __restrict__ out) {
    int row = blockIdx.x;
    int t = threadIdx.x;
    const float4* xr = (const float4*)(x + (size_t)row * DIMD);
    float4 v = xr[t];
    float s  = v.x + v.y + v.z + v.w;
    float sq = v.x * v.x + v.y * v.y + v.z * v.z + v.w * v.w;
    #pragma unroll
    for (int o = 16; o > 0; o >>= 1) {
        s  += __shfl_xor_sync(0xffffffffu, s,  o);
        sq += __shfl_xor_sync(0xffffffffu, sq, o);
    }
    __shared__ float rs_[4], rq_[4];
    int lane = t & 31, w = t >> 5;
    if (lane == 0) { rs_[w] = s; rq_[w] = sq; }
    __syncthreads();
    s  = rs_[0] + rs_[1] + rs_[2] + rs_[3];
    sq = rq_[0] + rq_[1] + rq_[2] + rq_[3];
    float mu  = s * (1.0f / DIMD);
    float var = sq * (1.0f / DIMD) - mu * mu;
    float rstd = rsqrtf(var + 1e-5f);
    float4 gg = ((const float4*)g)[t];
    float4 bb = ((const float4*)be)[t];
    float4 o4;
    o4.x = (v.x - mu) * rstd * gg.x + bb.x;
    o4.y = (v.y - mu) * rstd * gg.y + bb.y;
    o4.z = (v.z - mu) * rstd * gg.z + bb.z;
    o4.w = (v.w - mu) * rstd * gg.w + bb.w;
    ((float4*)(out + (size_t)row * DIMD))[t] = o4;
}

// ---------------- tf32 tensor-core NN GEMM ----------------------------------
// C[M,N] = A[M,K] @ B[K,N] (+epilogue). BM=128, BN=128, BK=16, 256 threads.
// 8 warps: warpM = wid&1 (64 rows), warpN = wid>>1 (32 cols).
// Per warp: 4 m16-tiles x 4 n8-tiles of m16n8k8.
// EPI: 0=none, 1=+bias, 2=+bias,gelu, 3=+bias,+residual
// SPLIT: 0 = raw single-pass tf32, 1 = 3xTF32 hi/lo split (fp32 accuracy)
template <int EPI, int SPLIT>
__global__ __launch_bounds__(256) void gemm_tf32(
    const float* __restrict__ A, const float* __restrict__ Bm,
    const float* __restrict__ bias, const float* __restrict__ R,
    float* __restrict__ C, int M, int Ncols, int K)
{
    __shared__ float As_h[128][20];
    __shared__ float Bs_h[16][136];
    __shared__ float As_l[SPLIT ? 128 : 1][SPLIT ? 20 : 1];
    __shared__ float Bs_l[SPLIT ? 16 : 1][SPLIT ? 136 : 1];

    int tid = threadIdx.x, wid = tid >> 5, lane = tid & 31;
    int gid = lane >> 2, tg = lane & 3;
    int warpM = wid & 1, warpN = wid >> 1;
    int rowTile = blockIdx.y * 128, colTile = blockIdx.x * 128;

    float acc[4][4][4] = {};

    for (int k0 = 0; k0 < K; k0 += 16) {
        // ---- load A tile 128x16 ----
        #pragma unroll
        for (int i = 0; i < 2; i++) {
            int idx = tid + i * 256;
            int r = idx >> 2, c4 = (idx & 3) * 4;
            float4 a = *(const float4*)(A + (size_t)(rowTile + r) * K + k0 + c4);
            if constexpr (SPLIT) {
                float h0,l0,h1,l1,h2,l2,h3,l3;
                split_tf32(a.x,h0,l0); split_tf32(a.y,h1,l1);
                split_tf32(a.z,h2,l2); split_tf32(a.w,h3,l3);
                *(float4*)&As_h[r][c4] = make_float4(h0,h1,h2,h3);
                *(float4*)&As_l[r][c4] = make_float4(l0,l1,l2,l3);
            } else {
                *(float4*)&As_h[r][c4] = a;
            }
        }
        // ---- load B tile 16x128 ----
        #pragma unroll
        for (int i = 0; i < 2; i++) {
            int idx = tid + i * 256;
            int r = idx >> 5, c4 = (idx & 31) * 4;
            float4 b = *(const float4*)(Bm + (size_t)(k0 + r) * Ncols + colTile + c4);
            if constexpr (SPLIT) {
                float h0,l0,h1,l1,h2,l2,h3,l3;
                split_tf32(b.x,h0,l0); split_tf32(b.y,h1,l1);
                split_tf32(b.z,h2,l2); split_tf32(b.w,h3,l3);
                *(float4*)&Bs_h[r][c4] = make_float4(h0,h1,h2,h3);
                *(float4*)&Bs_l[r][c4] = make_float4(l0,l1,l2,l3);
            } else {
                *(float4*)&Bs_h[r][c4] = b;
            }
        }
        __syncthreads();

        #pragma unroll
        for (int ks = 0; ks < 16; ks += 8) {
            uint32_t af[4][4], bf[4][2];
            uint32_t al[SPLIT ? 4 : 1][4], bl[SPLIT ? 4 : 1][2];
            #pragma unroll
            for (int mt = 0; mt < 4; mt++) {
                int rb = warpM * 64 + mt * 16;
                af[mt][0] = __float_as_uint(As_h[rb + gid    ][ks + tg    ]);
                af[mt][1] = __float_as_uint(As_h[rb + gid + 8][ks + tg    ]);
                af[mt][2] = __float_as_uint(As_h[rb + gid    ][ks + tg + 4]);
                af[mt][3] = __float_as_uint(As_h[rb + gid + 8][ks + tg + 4]);
                if constexpr (SPLIT) {
                    al[mt][0] = __float_as_uint(As_l[rb + gid    ][ks + tg    ]);
                    al[mt][1] = __float_as_uint(As_l[rb + gid + 8][ks + tg    ]);
                    al[mt][2] = __float_as_uint(As_l[rb + gid    ][ks + tg + 4]);
                    al[mt][3] = __float_as_uint(As_l[rb + gid + 8][ks + tg + 4]);
                }
            }
            #pragma unroll
            for (int nt = 0; nt < 4; nt++) {
                int nb = warpN * 32 + nt * 8;
                bf[nt][0] = __float_as_uint(Bs_h[ks + tg    ][nb + gid]);
                bf[nt][1] = __float_as_uint(Bs_h[ks + tg + 4][nb + gid]);
                if constexpr (SPLIT) {
                    bl[nt][0] = __float_as_uint(Bs_l[ks + tg    ][nb + gid]);
                    bl[nt][1] = __float_as_uint(Bs_l[ks + tg + 4][nb + gid]);
                }
            }
            #pragma unroll
            for (int mt = 0; mt < 4; mt++)
                #pragma unroll
                for (int nt = 0; nt < 4; nt++) {
                    mma_tf32(acc[mt][nt], af[mt], bf[nt]);
                    if constexpr (SPLIT) {
                        mma_tf32(acc[mt][nt], af[mt], bl[nt]);
                        mma_tf32(acc[mt][nt], al[mt], bf[nt]);
                    }
                }
        }
        __syncthreads();
    }

    // ---- epilogue ----
    #pragma unroll
    for (int mt = 0; mt < 4; mt++) {
        #pragma unroll
        for (int nt = 0; nt < 4; nt++) {
            int col  = colTile + warpN * 32 + nt * 8 + tg * 2;
            int row0 = rowTile + warpM * 64 + mt * 16 + gid;
            int row1 = row0 + 8;
            float2 o0 = make_float2(acc[mt][nt][0], acc[mt][nt][1]);
            float2 o1 = make_float2(acc[mt][nt][2], acc[mt][nt][3]);
            if (EPI >= 1) {
                float b0 = bias[col], b1 = bias[col + 1];
                o0.x += b0; o0.y += b1; o1.x += b0; o1.y += b1;
            }
            if (EPI == 2) {
                o0.x = gelu_exact(o0.x); o0.y = gelu_exact(o0.y);
                o1.x = gelu_exact(o1.x); o1.y = gelu_exact(o1.y);
            }
            if (EPI == 3) {
                const float* r0p = R + (size_t)row0 * Ncols + col;
                const float* r1p = R + (size_t)row1 * Ncols + col;
                o0.x += r0p[0]; o0.y += r0p[1];
                o1.x += r1p[0]; o1.y += r1p[1];
            }
            *(float2*)(C + (size_t)row0 * Ncols + col) = o0;
            *(float2*)(C + (size_t)row1 * Ncols + col) = o1;
        }
    }
}

// ---------------- Attention scores via tf32 mma: S = (Q @ K^T)/8 ------------
// Per (b,h): M=N=4096, K=64. BM=BN=128, BK=16, 256 thr, single-pass tf32.
__global__ __launch_bounds__(256) void score_tf32(
    const float* __restrict__ q, const float* __restrict__ k, float* __restrict__ S)
{
    int z = blockIdx.z, b = z >> 3, hh = z & 7;
    const float* A  = q + (size_t)b * SEQ * DIMD + hh * HD;
    const float* Bp = k + (size_t)b * SEQ * DIMD + hh * HD;
    float* C = S + (size_t)z * SEQ * SEQ;

    __shared__ float As[128][20];
    __shared__ float Bs[16][132];

    int tid = threadIdx.x, wid = tid >> 5, lane = tid & 31;
    int gid = lane >> 2, tg = lane & 3;
    int warpM = wid & 1, warpN = wid >> 1;
    int rowTile = blockIdx.y * 128, colTile = blockIdx.x * 128;

    float acc[4][4][4] = {};

    for (int k0 = 0; k0 < HD; k0 += 16) {
        #pragma unroll
        for (int i = 0; i < 2; i++) {
            int idx = tid + i * 256;
            int r = idx >> 2, c4 = (idx & 3) * 4;
            float4 a = *(const float4*)(A + (size_t)(rowTile + r) * DIMD + k0 + c4);
            *(float4*)&As[r][c4] = a;
        }
        #pragma unroll
        for (int i = 0; i < 2; i++) {
            int idx = tid + i * 256;
            int n = idx >> 2, kc4 = (idx & 3) * 4;
            float4 bb = *(const float4*)(Bp + (size_t)(colTile + n) * DIMD + k0 + kc4);
            Bs[kc4 + 0][n] = bb.x;  Bs[kc4 + 1][n] = bb.y;
            Bs[kc4 + 2][n] = bb.z;  Bs[kc4 + 3][n] = bb.w;
        }
        __syncthreads();

        #pragma unroll
        for (int ks = 0; ks < 16; ks += 8) {
            uint32_t af[4][4], bf[4][2];
            #pragma unroll
            for (int mt = 0; mt < 4; mt++) {
                int rb = warpM * 64 + mt * 16;
                af[mt][0] = __float_as_uint(As[rb + gid    ][ks + tg    ]);
                af[mt][1] = __float_as_uint(As[rb + gid + 8][ks + tg    ]);
                af[mt][2] = __float_as_uint(As[rb + gid    ][ks + tg + 4]);
                af[mt][3] = __float_as_uint(As[rb + gid + 8][ks + tg + 4]);
            }
            #pragma unroll
            for (int nt = 0; nt < 4; nt++) {
                int nb = warpN * 32 + nt * 8;
                bf[nt][0] = __float_as_uint(Bs[ks + tg    ][nb + gid]);
                bf[nt][1] = __float_as_uint(Bs[ks + tg + 4][nb + gid]);
            }
            #pragma unroll
            for (int mt = 0; mt < 4; mt++)
                #pragma unroll
                for (int nt = 0; nt < 4; nt++)
                    mma_tf32(acc[mt][nt], af[mt], bf[nt]);
        }
        __syncthreads();
    }

    const float scale = 0.125f;
    #pragma unroll
    for (int mt = 0; mt < 4; mt++) {
        #pragma unroll
        for (int nt = 0; nt < 4; nt++) {
            int col  = colTile + warpN * 32 + nt * 8 + tg * 2;
            int row0 = rowTile + warpM * 64 + mt * 16 + gid;
            int row1 = row0 + 8;
            float2 o0 = make_float2(acc[mt][nt][0] * scale, acc[mt][nt][1] * scale);
            float2 o1 = make_float2(acc[mt][nt][2] * scale, acc[mt][nt][3] * scale);
            *(float2*)(C + (size_t)row0 * SEQ + col) = o0;
            *(float2*)(C + (size_t)row1 * SEQ + col) = o1;
        }
    }
}

// ---------------- Row softmax over 4096, in-place ---------------------------
__global__ void softmax_kernel(float* __restrict__ S) {
    size_t base = (size_t)blockIdx.x * SEQ;
    float4* p = (float4*)(S + base);
    int t = threadIdx.x;
    float4 v[4];
    #pragma unroll
    for (int i = 0; i < 4; i++) v[i] = p[i * 256 + t];
    float m = v[0].x;
    #pragma unroll
    for (int i = 0; i < 4; i++)
        m = fmaxf(m, fmaxf(fmaxf(v[i].x, v[i].y), fmaxf(v[i].z, v[i].w)));
    #pragma unroll
    for (int o = 16; o > 0; o >>= 1) m = fmaxf(m, __shfl_xor_sync(0xffffffffu, m, o));
    __shared__ float sm[8], ss[8];
    int lane = t & 31, w = t >> 5;
    if (lane == 0) sm[w] = m;
    __syncthreads();
    float mm = sm[0];
    #pragma unroll
    for (int i = 1; i < 8; i++) mm = fmaxf(mm, sm[i]);
    float s = 0.0f;
    #pragma unroll
    for (int i = 0; i < 4; i++) {
        v[i].x = __expf(v[i].x - mm); v[i].y = __expf(v[i].y - mm);
        v[i].z = __expf(v[i].z - mm); v[i].w = __expf(v[i].w - mm);
        s += v[i].x + v[i].y + v[i].z + v[i].w;
    }
    #pragma unroll
    for (int o = 16; o > 0; o >>= 1) s += __shfl_xor_sync(0xffffffffu, s, o);
    if (lane == 0) ss[w] = s;
    __syncthreads();
    float tot = ss[0] + ss[1] + ss[2] + ss[3] + ss[4] + ss[5] + ss[6] + ss[7];
    float r = 1.0f / tot;
    #pragma unroll
    for (int i = 0; i < 4; i++) {
        v[i].x *= r; v[i].y *= r; v[i].z *= r; v[i].w *= r;
        p[i * 256 + t] = v[i];
    }
}

// ---------------- PV via tf32 mma: att_head = P @ V -------------------------
// Per (b,h): M=4096, N=64, K=4096. BM=128, BN=64, BK=16, 256 thr.
// 8 warps: warpM = wid&3 (32 rows), warpN = wid>>2 (32 cols).
__global__ __launch_bounds__(256) void pv_tf32(
    const float* __restrict__ S, const float* __restrict__ v, float* __restrict__ att)
{
    int z = blockIdx.y, b = z >> 3, hh = z & 7;
    const float* A  = S   + (size_t)z * SEQ * SEQ;
    const float* Bp = v   + (size_t)b * SEQ * DIMD + hh * HD;
    float* C        = att + (size_t)b * SEQ * DIMD + hh * HD;

    __shared__ float As[128][20];
    __shared__ float Bs[16][72];

    int tid = threadIdx.x, wid = tid >> 5, lane = tid & 31;
    int gid = lane >> 2, tg = lane & 3;
    int warpM = wid & 3, warpN = wid >> 2;
    int rowTile = blockIdx.x * 128;

    float acc[2][4][4] = {};

    for (int k0 = 0; k0 < SEQ; k0 += 16) {
        #pragma unroll
        for (int i = 0; i < 2; i++) {
            int idx = tid + i * 256;
            int r = idx >> 2, c4 = (idx & 3) * 4;
            float4 a = *(const float4*)(A + (size_t)(rowTile + r) * SEQ + k0 + c4);
            *(float4*)&As[r][c4] = a;
        }
        {
            int r = tid >> 4, c4 = (tid & 15) * 4;
            float4 bb = *(const float4*)(Bp + (size_t)(k0 + r) * DIMD + c4);
            *(float4*)&Bs[r][c4] = bb;
        }
        __syncthreads();

        #pragma unroll
        for (int ks = 0; ks < 16; ks += 8) {
            uint32_t af[2][4], bf[4][2];
            #pragma unroll
            for (int mt = 0; mt < 2; mt++) {
                int rb = warpM * 32 + mt * 16;
                af[mt][0] = __float_as_uint(As[rb + gid    ][ks + tg    ]);
                af[mt][1] = __float_as_uint(As[rb + gid + 8][ks + tg    ]);
                af[mt][2] = __float_as_uint(As[rb + gid    ][ks + tg + 4]);
                af[mt][3] = __float_as_uint(As[rb + gid + 8][ks + tg + 4]);
            }
            #pragma unroll
            for (int nt = 0; nt < 4; nt++) {
                int nb = warpN * 32 + nt * 8;
                bf[nt][0] = __float_as_uint(Bs[ks + tg    ][nb + gid]);
                bf[nt][1] = __float_as_uint(Bs[ks + tg + 4][nb + gid]);
            }
            #pragma unroll
            for (int mt = 0; mt < 2; mt++)
                #pragma unroll
                for (int nt = 0; nt < 4; nt++)
                    mma_tf32(acc[mt][nt], af[mt], bf[nt]);
        }
        __syncthreads();
    }

    #pragma unroll
    for (int mt = 0; mt < 2; mt++) {
        #pragma unroll
        for (int nt = 0; nt < 4; nt++) {
            int col  = warpN * 32 + nt * 8 + tg * 2;
            int row0 = rowTile + warpM * 32 + mt * 16 + gid;
            int row1 = row0 + 8;
            *(float2*)(C + (size_t)row0 * DIMD + col) =
                make_float2(acc[mt][nt][0], acc[mt][nt][1]);
            *(float2*)(C + (size_t)row1 * DIMD + col) =
                make_float2(acc[mt][nt][2], acc[mt][nt][3]);
        }
    }
}

// ---------------- launch ----------------------------------------------------
extern "C" void kernel_launch(void* const* d_in, const int* in_sizes, int n_in,
                              void* d_out, int out_size) {
    const float* x   = (const float*)d_in[0];
    const float* Wq  = (const float*)d_in[1];
    const float* Wk  = (const float*)d_in[2];
    const float* Wv  = (const float*)d_in[3];
    const float* Wo  = (const float*)d_in[4];
    const float* bo  = (const float*)d_in[5];
    const float* W1  = (const float*)d_in[6];
    const float* b1  = (const float*)d_in[7];
    const float* W2  = (const float*)d_in[8];
    const float* b2  = (const float*)d_in[9];
    const float* g1  = (const float*)d_in[10];
    const float* be1 = (const float*)d_in[11];
    const float* g2  = (const float*)d_in[12];
    const float* be2 = (const float*)d_in[13];
    float* out = (float*)d_out;

    float *h, *q, *k, *v, *att, *xm, *ff, *S;
    cudaGetSymbolAddress((void**)&h,   g_h);
    cudaGetSymbolAddress((void**)&q,   g_q);
    cudaGetSymbolAddress((void**)&k,   g_k);
    cudaGetSymbolAddress((void**)&v,   g_v);
    cudaGetSymbolAddress((void**)&att, g_att);
    cudaGetSymbolAddress((void**)&xm,  g_xm);
    cudaGetSymbolAddress((void**)&ff,  g_ff);
    cudaGetSymbolAddress((void**)&S,   g_S);

    dim3 gProj(DIMD / 128, BN_TOK / 128);       // (4, 64)
    dim3 gMlp(MLPD / 128, BN_TOK / 128);        // (16, 64)

    // 1) h = LN(x; g1, be1)
    ln_kernel<<<BN_TOK, 128>>>(x, g1, be1, h);
    // 2) q, k, v projections (single-pass tf32 — attention path, error diluted)
    gemm_tf32<0, 0><<<gProj, 256>>>(h, Wq, nullptr, nullptr, q, BN_TOK, DIMD, DIMD);
    gemm_tf32<0, 0><<<gProj, 256>>>(h, Wk, nullptr, nullptr, k, BN_TOK, DIMD, DIMD);
    gemm_tf32<0, 0><<<gProj, 256>>>(h, Wv, nullptr, nullptr, v, BN_TOK, DIMD, DIMD);
    // 3) S = QK^T / sqrt(hd)
    score_tf32<<<dim3(SEQ / 128, SEQ / 128, BATCH * HEADS), 256>>>(q, k, S);
    // 4) softmax rows (fp32)
    softmax_kernel<<<BATCH * HEADS * SEQ, 256>>>(S);
    // 5) att = P @ V
    pv_tf32<<<dim3(SEQ / 128, BATCH * HEADS), 256>>>(S, v, att);
    // 6) xm = x + att @ Wo + bo  (single tf32 — attention residual is small)
    gemm_tf32<3, 0><<<gProj, 256>>>(att, Wo, bo, x, xm, BN_TOK, DIMD, DIMD);
    // 7) h = LN(xm; g2, be2)
    ln_kernel<<<BN_TOK, 128>>>(xm, g2, be2, h);
    // 8) ff = gelu(h @ W1 + b1)   (3xTF32 — full-weight residual path)
    gemm_tf32<2, 1><<<gMlp, 256>>>(h, W1, b1, nullptr, ff, BN_TOK, MLPD, DIMD);
    // 9) out = xm + ff @ W2 + b2  (3xTF32)
    gemm_tf32<3, 1><<<gProj, 256>>>(ff, W2, b2, xm, out, BN_TOK, DIMD, MLPD);
}

// round 8
// speedup vs baseline: 2.2541x; 1.8959x over previous
#include <cuda_runtime.h>
#include <math.h>
#include <stdint.h>

#define DIMD   512
#define HEADS  8
#define HD     64
#define MLPD   2048
#define BATCH  2
#define SEQ    4096
#define BN_TOK 8192   // BATCH*SEQ

// ---------------- scratch (static device arrays; no allocation) -------------
__device__ float g_h  [(size_t)BN_TOK * DIMD];
__device__ float g_q  [(size_t)BN_TOK * DIMD];
__device__ float g_k  [(size_t)BN_TOK * DIMD];
__device__ float g_v  [(size_t)BN_TOK * DIMD];
__device__ float g_att[(size_t)BN_TOK * DIMD];
__device__ float g_xm [(size_t)BN_TOK * DIMD];
__device__ float g_ff [(size_t)BN_TOK * MLPD];

__device__ __forceinline__ float gelu_exact(float x) {
    return 0.5f * x * (1.0f + erff(x * 0.70710678118654752440f));
}

// tf32 helpers ---------------------------------------------------------------
__device__ __forceinline__ void split_tf32(float x, float& hi, float& lo) {
    uint32_t hb;
    asm("cvt.rna.tf32.f32 %0, %1;" : "=r"(hb) : "f"(x));
    hi = __uint_as_float(hb);
    float l = x - hi;
    uint32_t lb;
    asm("cvt.rna.tf32.f32 %0, %1;" : "=r"(lb) : "f"(l));
    lo = __uint_as_float(lb);
}

__device__ __forceinline__ void mma_tf32(float* c, const uint32_t* a, const uint32_t* b) {
    asm volatile(
        "mma.sync.aligned.m16n8k8.row.col.f32.tf32.tf32.f32 "
        "{%0,%1,%2,%3},{%4,%5,%6,%7},{%8,%9},{%0,%1,%2,%3};\n"
        : "+f"(c[0]), "+f"(c[1]), "+f"(c[2]), "+f"(c[3])
        : "r"(a[0]), "r"(a[1]), "r"(a[2]), "r"(a[3]), "r"(b[0]), "r"(b[1]));
}

// ---------------- LayerNorm: one block (128 thr) per row of 512 -------------
__global__ void ln_kernel(const float* __restrict__ x, const float* __restrict__ g,
                          const float* __restrict__ be, float* __restrict__ out) {
    int row = blockIdx.x;
    int t = threadIdx.x;
    const float4* xr = (const float4*)(x + (size_t)row * DIMD);
    float4 v = xr[t];
    float s  = v.x + v.y + v.z + v.w;
    float sq = v.x * v.x + v.y * v.y + v.z * v.z + v.w * v.w;
    #pragma unroll
    for (int o = 16; o > 0; o >>= 1) {
        s  += __shfl_xor_sync(0xffffffffu, s,  o);
        sq += __shfl_xor_sync(0xffffffffu, sq, o);
    }
    __shared__ float rs_[4], rq_[4];
    int lane = t & 31, w = t >> 5;
    if (lane == 0) { rs_[w] = s; rq_[w] = sq; }
    __syncthreads();
    s  = rs_[0] + rs_[1] + rs_[2] + rs_[3];
    sq = rq_[0] + rq_[1] + rq_[2] + rq_[3];
    float mu  = s * (1.0f / DIMD);
    float var = sq * (1.0f / DIMD) - mu * mu;
    float rstd = rsqrtf(var + 1e-5f);
    float4 gg = ((const float4*)g)[t];
    float4 bb = ((const float4*)be)[t];
    float4 o4;
    o4.x = (v.x - mu) * rstd * gg.x + bb.x;
    o4.y = (v.y - mu) * rstd * gg.y + bb.y;
    o4.z = (v.z - mu) * rstd * gg.z + bb.z;
    o4.w = (v.w - mu) * rstd * gg.w + bb.w;
    ((float4*)(out + (size_t)row * DIMD))[t] = o4;
}

// ---------------- tf32 tensor-core NN GEMM ----------------------------------
// C[M,N] = A[M,K] @ B[K,N] (+epilogue). BM=128, BN=128, BK=16, 256 threads.
// EPI: 0=none, 1=+bias, 2=+bias,gelu, 3=+bias,+residual
// SPLIT: 0 = raw single-pass tf32, 1 = 3xTF32 hi/lo split (fp32 accuracy)
template <int EPI, int SPLIT>
__global__ __launch_bounds__(256) void gemm_tf32(
    const float* __restrict__ A, const float* __restrict__ Bm,
    const float* __restrict__ bias, const float* __restrict__ R,
    float* __restrict__ C, int M, int Ncols, int K)
{
    __shared__ float As_h[128][20];
    __shared__ float Bs_h[16][136];
    __shared__ float As_l[SPLIT ? 128 : 1][SPLIT ? 20 : 1];
    __shared__ float Bs_l[SPLIT ? 16 : 1][SPLIT ? 136 : 1];

    int tid = threadIdx.x, wid = tid >> 5, lane = tid & 31;
    int gid = lane >> 2, tg = lane & 3;
    int warpM = wid & 1, warpN = wid >> 1;
    int rowTile = blockIdx.y * 128, colTile = blockIdx.x * 128;

    float acc[4][4][4] = {};

    for (int k0 = 0; k0 < K; k0 += 16) {
        #pragma unroll
        for (int i = 0; i < 2; i++) {
            int idx = tid + i * 256;
            int r = idx >> 2, c4 = (idx & 3) * 4;
            float4 a = *(const float4*)(A + (size_t)(rowTile + r) * K + k0 + c4);
            if constexpr (SPLIT) {
                float h0,l0,h1,l1,h2,l2,h3,l3;
                split_tf32(a.x,h0,l0); split_tf32(a.y,h1,l1);
                split_tf32(a.z,h2,l2); split_tf32(a.w,h3,l3);
                *(float4*)&As_h[r][c4] = make_float4(h0,h1,h2,h3);
                *(float4*)&As_l[r][c4] = make_float4(l0,l1,l2,l3);
            } else {
                *(float4*)&As_h[r][c4] = a;
            }
        }
        #pragma unroll
        for (int i = 0; i < 2; i++) {
            int idx = tid + i * 256;
            int r = idx >> 5, c4 = (idx & 31) * 4;
            float4 b = *(const float4*)(Bm + (size_t)(k0 + r) * Ncols + colTile + c4);
            if constexpr (SPLIT) {
                float h0,l0,h1,l1,h2,l2,h3,l3;
                split_tf32(b.x,h0,l0); split_tf32(b.y,h1,l1);
                split_tf32(b.z,h2,l2); split_tf32(b.w,h3,l3);
                *(float4*)&Bs_h[r][c4] = make_float4(h0,h1,h2,h3);
                *(float4*)&Bs_l[r][c4] = make_float4(l0,l1,l2,l3);
            } else {
                *(float4*)&Bs_h[r][c4] = b;
            }
        }
        __syncthreads();

        #pragma unroll
        for (int ks = 0; ks < 16; ks += 8) {
            uint32_t af[4][4], bf[4][2];
            uint32_t al[SPLIT ? 4 : 1][4], bl[SPLIT ? 4 : 1][2];
            #pragma unroll
            for (int mt = 0; mt < 4; mt++) {
                int rb = warpM * 64 + mt * 16;
                af[mt][0] = __float_as_uint(As_h[rb + gid    ][ks + tg    ]);
                af[mt][1] = __float_as_uint(As_h[rb + gid + 8][ks + tg    ]);
                af[mt][2] = __float_as_uint(As_h[rb + gid    ][ks + tg + 4]);
                af[mt][3] = __float_as_uint(As_h[rb + gid + 8][ks + tg + 4]);
                if constexpr (SPLIT) {
                    al[mt][0] = __float_as_uint(As_l[rb + gid    ][ks + tg    ]);
                    al[mt][1] = __float_as_uint(As_l[rb + gid + 8][ks + tg    ]);
                    al[mt][2] = __float_as_uint(As_l[rb + gid    ][ks + tg + 4]);
                    al[mt][3] = __float_as_uint(As_l[rb + gid + 8][ks + tg + 4]);
                }
            }
            #pragma unroll
            for (int nt = 0; nt < 4; nt++) {
                int nb = warpN * 32 + nt * 8;
                bf[nt][0] = __float_as_uint(Bs_h[ks + tg    ][nb + gid]);
                bf[nt][1] = __float_as_uint(Bs_h[ks + tg + 4][nb + gid]);
                if constexpr (SPLIT) {
                    bl[nt][0] = __float_as_uint(Bs_l[ks + tg    ][nb + gid]);
                    bl[nt][1] = __float_as_uint(Bs_l[ks + tg + 4][nb + gid]);
                }
            }
            #pragma unroll
            for (int mt = 0; mt < 4; mt++)
                #pragma unroll
                for (int nt = 0; nt < 4; nt++) {
                    mma_tf32(acc[mt][nt], af[mt], bf[nt]);
                    if constexpr (SPLIT) {
                        mma_tf32(acc[mt][nt], af[mt], bl[nt]);
                        mma_tf32(acc[mt][nt], al[mt], bf[nt]);
                    }
                }
        }
        __syncthreads();
    }

    #pragma unroll
    for (int mt = 0; mt < 4; mt++) {
        #pragma unroll
        for (int nt = 0; nt < 4; nt++) {
            int col  = colTile + warpN * 32 + nt * 8 + tg * 2;
            int row0 = rowTile + warpM * 64 + mt * 16 + gid;
            int row1 = row0 + 8;
            float2 o0 = make_float2(acc[mt][nt][0], acc[mt][nt][1]);
            float2 o1 = make_float2(acc[mt][nt][2], acc[mt][nt][3]);
            if (EPI >= 1) {
                float b0 = bias[col], b1 = bias[col + 1];
                o0.x += b0; o0.y += b1; o1.x += b0; o1.y += b1;
            }
            if (EPI == 2) {
                o0.x = gelu_exact(o0.x); o0.y = gelu_exact(o0.y);
                o1.x = gelu_exact(o1.x); o1.y = gelu_exact(o1.y);
            }
            if (EPI == 3) {
                const float* r0p = R + (size_t)row0 * Ncols + col;
                const float* r1p = R + (size_t)row1 * Ncols + col;
                o0.x += r0p[0]; o0.y += r0p[1];
                o1.x += r1p[0]; o1.y += r1p[1];
            }
            *(float2*)(C + (size_t)row0 * Ncols + col) = o0;
            *(float2*)(C + (size_t)row1 * Ncols + col) = o1;
        }
    }
}

// ---------------- Flash attention (tf32 MMA, online softmax) ----------------
// Per CTA: 64 Q rows of one (b,h). 128 threads = 4 warps, warp w -> rows
// w*16..w*16+15. Loop over KV tiles of 64. S never materialized.
// Q fragments in registers (pre-scaled by 1/8). P routed through smem
// (C-fragment -> A-fragment layout change). smem stride 68 -> all fragment
// LDS patterns are bank-conflict-free (banks = 4*gid + tg [+const]).
#define FLDS 68
#define FSM_BYTES (3 * 64 * FLDS * 4)

__global__ __launch_bounds__(128, 3) void flash_tf32(
    const float* __restrict__ qp, const float* __restrict__ kp,
    const float* __restrict__ vp, float* __restrict__ att)
{
    extern __shared__ float sm_[];
    float* Ks = sm_;
    float* Vs = sm_ + 64 * FLDS;
    float* Ps = sm_ + 2 * 64 * FLDS;   // also Q staging

    int z = blockIdx.y, b = z >> 3, hh = z & 7;
    const float* Q = qp + (size_t)b * SEQ * DIMD + hh * HD;
    const float* K = kp + (size_t)b * SEQ * DIMD + hh * HD;
    const float* V = vp + (size_t)b * SEQ * DIMD + hh * HD;
    float* O = att + (size_t)b * SEQ * DIMD + hh * HD;
    int q0 = blockIdx.x * 64;

    int tid = threadIdx.x, wid = tid >> 5, lane = tid & 31;
    int gid = lane >> 2, tg = lane & 3;
    int rb = wid * 16;

    // ---- stage Q (scaled by 1/sqrt(hd)=0.125), extract fragments ----
    for (int idx = tid; idx < 64 * 16; idx += 128) {
        int r = idx >> 4, c4 = (idx & 15) * 4;
        float4 a = *(const float4*)(Q + (size_t)(q0 + r) * DIMD + c4);
        a.x *= 0.125f; a.y *= 0.125f; a.z *= 0.125f; a.w *= 0.125f;
        *(float4*)&Ps[r * FLDS + c4] = a;
    }
    __syncthreads();
    uint32_t qf[8][4];
    #pragma unroll
    for (int ki = 0; ki < 8; ki++) {
        int ks = ki * 8;
        qf[ki][0] = __float_as_uint(Ps[(rb + gid    ) * FLDS + ks + tg    ]);
        qf[ki][1] = __float_as_uint(Ps[(rb + gid + 8) * FLDS + ks + tg    ]);
        qf[ki][2] = __float_as_uint(Ps[(rb + gid    ) * FLDS + ks + tg + 4]);
        qf[ki][3] = __float_as_uint(Ps[(rb + gid + 8) * FLDS + ks + tg + 4]);
    }
    __syncthreads();

    float m0 = -1e30f, m1 = -1e30f, l0 = 0.0f, l1 = 0.0f;
    float o[8][4] = {};

    for (int t0 = 0; t0 < SEQ; t0 += 64) {
        // ---- load K,V tiles (row-major, stride FLDS) ----
        for (int idx = tid; idx < 64 * 16; idx += 128) {
            int r = idx >> 4, c4 = (idx & 15) * 4;
            *(float4*)&Ks[r * FLDS + c4] =
                *(const float4*)(K + (size_t)(t0 + r) * DIMD + c4);
            *(float4*)&Vs[r * FLDS + c4] =
                *(const float4*)(V + (size_t)(t0 + r) * DIMD + c4);
        }
        __syncthreads();

        // ---- S = Q @ K^T (scaled) ----
        float s[8][4] = {};
        #pragma unroll
        for (int ki = 0; ki < 8; ki++) {
            int ks = ki * 8;
            #pragma unroll
            for (int nt = 0; nt < 8; nt++) {
                uint32_t bf[2];
                bf[0] = __float_as_uint(Ks[(nt * 8 + gid) * FLDS + ks + tg    ]);
                bf[1] = __float_as_uint(Ks[(nt * 8 + gid) * FLDS + ks + tg + 4]);
                mma_tf32(s[nt], qf[ki], bf);
            }
        }

        // ---- online softmax ----
        float tm0 = -1e30f, tm1 = -1e30f;
        #pragma unroll
        for (int nt = 0; nt < 8; nt++) {
            tm0 = fmaxf(tm0, fmaxf(s[nt][0], s[nt][1]));
            tm1 = fmaxf(tm1, fmaxf(s[nt][2], s[nt][3]));
        }
        tm0 = fmaxf(tm0, __shfl_xor_sync(0xffffffffu, tm0, 1));
        tm0 = fmaxf(tm0, __shfl_xor_sync(0xffffffffu, tm0, 2));
        tm1 = fmaxf(tm1, __shfl_xor_sync(0xffffffffu, tm1, 1));
        tm1 = fmaxf(tm1, __shfl_xor_sync(0xffffffffu, tm1, 2));
        float nm0 = fmaxf(m0, tm0), nm1 = fmaxf(m1, tm1);
        float r0 = __expf(m0 - nm0), r1 = __expf(m1 - nm1);
        float sum0 = 0.0f, sum1 = 0.0f;
        #pragma unroll
        for (int nt = 0; nt < 8; nt++) {
            s[nt][0] = __expf(s[nt][0] - nm0);
            s[nt][1] = __expf(s[nt][1] - nm0);
            s[nt][2] = __expf(s[nt][2] - nm1);
            s[nt][3] = __expf(s[nt][3] - nm1);
            sum0 += s[nt][0] + s[nt][1];
            sum1 += s[nt][2] + s[nt][3];
        }
        sum0 += __shfl_xor_sync(0xffffffffu, sum0, 1);
        sum0 += __shfl_xor_sync(0xffffffffu, sum0, 2);
        sum1 += __shfl_xor_sync(0xffffffffu, sum1, 1);
        sum1 += __shfl_xor_sync(0xffffffffu, sum1, 2);
        l0 = l0 * r0 + sum0;
        l1 = l1 * r1 + sum1;
        m0 = nm0; m1 = nm1;
        #pragma unroll
        for (int nt = 0; nt < 8; nt++) {
            o[nt][0] *= r0; o[nt][1] *= r0;
            o[nt][2] *= r1; o[nt][3] *= r1;
        }

        // ---- P -> smem (C layout -> A layout) ----
        #pragma unroll
        for (int nt = 0; nt < 8; nt++) {
            *(float2*)&Ps[(rb + gid    ) * FLDS + nt * 8 + tg * 2] =
                make_float2(s[nt][0], s[nt][1]);
            *(float2*)&Ps[(rb + gid + 8) * FLDS + nt * 8 + tg * 2] =
                make_float2(s[nt][2], s[nt][3]);
        }
        __syncthreads();

        // ---- O += P @ V ----
        #pragma unroll
        for (int ki = 0; ki < 8; ki++) {
            int ks = ki * 8;
            uint32_t af[4];
            af[0] = __float_as_uint(Ps[(rb + gid    ) * FLDS + ks + tg    ]);
            af[1] = __float_as_uint(Ps[(rb + gid + 8) * FLDS + ks + tg    ]);
            af[2] = __float_as_uint(Ps[(rb + gid    ) * FLDS + ks + tg + 4]);
            af[3] = __float_as_uint(Ps[(rb + gid + 8) * FLDS + ks + tg + 4]);
            #pragma unroll
            for (int nt = 0; nt < 8; nt++) {
                uint32_t bf[2];
                bf[0] = __float_as_uint(Vs[(ks + tg    ) * FLDS + nt * 8 + gid]);
                bf[1] = __float_as_uint(Vs[(ks + tg + 4) * FLDS + nt * 8 + gid]);
                mma_tf32(o[nt], af, bf);
            }
        }
        __syncthreads();
    }

    // ---- normalize and write ----
    float inv0 = 1.0f / l0, inv1 = 1.0f / l1;
    int row0 = q0 + rb + gid, row1 = row0 + 8;
    #pragma unroll
    for (int nt = 0; nt < 8; nt++) {
        int col = nt * 8 + tg * 2;
        *(float2*)(O + (size_t)row0 * DIMD + col) =
            make_float2(o[nt][0] * inv0, o[nt][1] * inv0);
        *(float2*)(O + (size_t)row1 * DIMD + col) =
            make_float2(o[nt][2] * inv1, o[nt][3] * inv1);
    }
}

// ---------------- launch ----------------------------------------------------
extern "C" void kernel_launch(void* const* d_in, const int* in_sizes, int n_in,
                              void* d_out, int out_size) {
    const float* x   = (const float*)d_in[0];
    const float* Wq  = (const float*)d_in[1];
    const float* Wk  = (const float*)d_in[2];
    const float* Wv  = (const float*)d_in[3];
    const float* Wo  = (const float*)d_in[4];
    const float* bo  = (const float*)d_in[5];
    const float* W1  = (const float*)d_in[6];
    const float* b1  = (const float*)d_in[7];
    const float* W2  = (const float*)d_in[8];
    const float* b2  = (const float*)d_in[9];
    const float* g1  = (const float*)d_in[10];
    const float* be1 = (const float*)d_in[11];
    const float* g2  = (const float*)d_in[12];
    const float* be2 = (const float*)d_in[13];
    float* out = (float*)d_out;

    float *h, *q, *k, *v, *att, *xm, *ff;
    cudaGetSymbolAddress((void**)&h,   g_h);
    cudaGetSymbolAddress((void**)&q,   g_q);
    cudaGetSymbolAddress((void**)&k,   g_k);
    cudaGetSymbolAddress((void**)&v,   g_v);
    cudaGetSymbolAddress((void**)&att, g_att);
    cudaGetSymbolAddress((void**)&xm,  g_xm);
    cudaGetSymbolAddress((void**)&ff,  g_ff);

    cudaFuncSetAttribute(flash_tf32,
                         cudaFuncAttributeMaxDynamicSharedMemorySize, FSM_BYTES);

    dim3 gProj(DIMD / 128, BN_TOK / 128);       // (4, 64)
    dim3 gMlp(MLPD / 128, BN_TOK / 128);        // (16, 64)

    // 1) h = LN(x; g1, be1)
    ln_kernel<<<BN_TOK, 128>>>(x, g1, be1, h);
    // 2) q, k, v projections (single-pass tf32)
    gemm_tf32<0, 0><<<gProj, 256>>>(h, Wq, nullptr, nullptr, q, BN_TOK, DIMD, DIMD);
    gemm_tf32<0, 0><<<gProj, 256>>>(h, Wk, nullptr, nullptr, k, BN_TOK, DIMD, DIMD);
    gemm_tf32<0, 0><<<gProj, 256>>>(h, Wv, nullptr, nullptr, v, BN_TOK, DIMD, DIMD);
    // 3-5) fused flash attention: att = softmax(QK^T/8) @ V
    flash_tf32<<<dim3(SEQ / 64, BATCH * HEADS), 128, FSM_BYTES>>>(q, k, v, att);
    // 6) xm = x + att @ Wo + bo
    gemm_tf32<3, 0><<<gProj, 256>>>(att, Wo, bo, x, xm, BN_TOK, DIMD, DIMD);
    // 7) h = LN(xm; g2, be2)
    ln_kernel<<<BN_TOK, 128>>>(xm, g2, be2, h);
    // 8) ff = gelu(h @ W1 + b1)   (3xTF32 split)
    gemm_tf32<2, 1><<<gMlp, 256>>>(h, W1, b1, nullptr, ff, BN_TOK, MLPD, DIMD);
    // 9) out = xm + ff @ W2 + b2  (3xTF32 split)
    gemm_tf32<3, 1><<<gProj, 256>>>(ff, W2, b2, xm, out, BN_TOK, DIMD, MLPD);
}

// round 9
// speedup vs baseline: 2.7094x; 1.2020x over previous
#include <cuda_runtime.h>
#include <cuda_bf16.h>
#include <math.h>
#include <stdint.h>

#define DIMD   512
#define HEADS  8
#define HD     64
#define MLPD   2048
#define BATCH  2
#define SEQ    4096
#define BN_TOK 8192   // BATCH*SEQ

// ---------------- scratch (static device arrays; no allocation) -------------
__device__ float g_h  [(size_t)BN_TOK * DIMD];
__device__ float g_q  [(size_t)BN_TOK * DIMD];
__device__ float g_k  [(size_t)BN_TOK * DIMD];
__device__ float g_v  [(size_t)BN_TOK * DIMD];
__device__ float g_att[(size_t)BN_TOK * DIMD];
__device__ float g_xm [(size_t)BN_TOK * DIMD];
__device__ float g_ff [(size_t)BN_TOK * MLPD];

__device__ __forceinline__ float gelu_exact(float x) {
    return 0.5f * x * (1.0f + erff(x * 0.70710678118654752440f));
}

// tf32 helpers ---------------------------------------------------------------
__device__ __forceinline__ void mma_tf32(float* c, const uint32_t* a, const uint32_t* b) {
    asm volatile(
        "mma.sync.aligned.m16n8k8.row.col.f32.tf32.tf32.f32 "
        "{%0,%1,%2,%3},{%4,%5,%6,%7},{%8,%9},{%0,%1,%2,%3};\n"
        : "+f"(c[0]), "+f"(c[1]), "+f"(c[2]), "+f"(c[3])
        : "r"(a[0]), "r"(a[1]), "r"(a[2]), "r"(a[3]), "r"(b[0]), "r"(b[1]));
}

// bf16 helpers ---------------------------------------------------------------
__device__ __forceinline__ void mma_bf16(float* c, const uint32_t* a, const uint32_t* b) {
    asm volatile(
        "mma.sync.aligned.m16n8k16.row.col.f32.bf16.bf16.f32 "
        "{%0,%1,%2,%3},{%4,%5,%6,%7},{%8,%9},{%0,%1,%2,%3};\n"
        : "+f"(c[0]), "+f"(c[1]), "+f"(c[2]), "+f"(c[3])
        : "r"(a[0]), "r"(a[1]), "r"(a[2]), "r"(a[3]), "r"(b[0]), "r"(b[1]));
}

__device__ __forceinline__ uint32_t pack2_bf16(float a, float b) {
    __nv_bfloat162 t = __floats2bfloat162_rn(a, b);   // .x = a (low), .y = b (high)
    return *reinterpret_cast<uint32_t*>(&t);
}

__device__ __forceinline__ void split_bf16(float x, float& hi, float& lo) {
    hi = __bfloat162float(__float2bfloat16_rn(x));
    lo = x - hi;
}

// ---------------- LayerNorm: one block (128 thr) per row of 512 -------------
__global__ void ln_kernel(const float* __restrict__ x, const float* __restrict__ g,
                          const float* __restrict__ be, float* __restrict__ out) {
    int row = blockIdx.x;
    int t = threadIdx.x;
    const float4* xr = (const float4*)(x + (size_t)row * DIMD);
    float4 v = xr[t];
    float s  = v.x + v.y + v.z + v.w;
    float sq = v.x * v.x + v.y * v.y + v.z * v.z + v.w * v.w;
    #pragma unroll
    for (int o = 16; o > 0; o >>= 1) {
        s  += __shfl_xor_sync(0xffffffffu, s,  o);
        sq += __shfl_xor_sync(0xffffffffu, sq, o);
    }
    __shared__ float rs_[4], rq_[4];
    int lane = t & 31, w = t >> 5;
    if (lane == 0) { rs_[w] = s; rq_[w] = sq; }
    __syncthreads();
    s  = rs_[0] + rs_[1] + rs_[2] + rs_[3];
    sq = rq_[0] + rq_[1] + rq_[2] + rq_[3];
    float mu  = s * (1.0f / DIMD);
    float var = sq * (1.0f / DIMD) - mu * mu;
    float rstd = rsqrtf(var + 1e-5f);
    float4 gg = ((const float4*)g)[t];
    float4 bb = ((const float4*)be)[t];
    float4 o4;
    o4.x = (v.x - mu) * rstd * gg.x + bb.x;
    o4.y = (v.y - mu) * rstd * gg.y + bb.y;
    o4.z = (v.z - mu) * rstd * gg.z + bb.z;
    o4.w = (v.w - mu) * rstd * gg.w + bb.w;
    ((float4*)(out + (size_t)row * DIMD))[t] = o4;
}

// ---------------- tf32 tensor-core NN GEMM (single-pass) --------------------
// C[M,N] = A[M,K] @ B[K,N] (+epilogue). BM=128, BN=128, BK=16, 256 threads.
// EPI: 0=none, 1=+bias, 2=+bias,gelu, 3=+bias,+residual
template <int EPI>
__global__ __launch_bounds__(256) void gemm_tf32(
    const float* __restrict__ A, const float* __restrict__ Bm,
    const float* __restrict__ bias, const float* __restrict__ R,
    float* __restrict__ C, int M, int Ncols, int K)
{
    __shared__ float As_h[128][20];
    __shared__ float Bs_h[16][136];

    int tid = threadIdx.x, wid = tid >> 5, lane = tid & 31;
    int gid = lane >> 2, tg = lane & 3;
    int warpM = wid & 1, warpN = wid >> 1;
    int rowTile = blockIdx.y * 128, colTile = blockIdx.x * 128;

    float acc[4][4][4] = {};

    for (int k0 = 0; k0 < K; k0 += 16) {
        #pragma unroll
        for (int i = 0; i < 2; i++) {
            int idx = tid + i * 256;
            int r = idx >> 2, c4 = (idx & 3) * 4;
            float4 a = *(const float4*)(A + (size_t)(rowTile + r) * K + k0 + c4);
            *(float4*)&As_h[r][c4] = a;
        }
        #pragma unroll
        for (int i = 0; i < 2; i++) {
            int idx = tid + i * 256;
            int r = idx >> 5, c4 = (idx & 31) * 4;
            float4 b = *(const float4*)(Bm + (size_t)(k0 + r) * Ncols + colTile + c4);
            *(float4*)&Bs_h[r][c4] = b;
        }
        __syncthreads();

        #pragma unroll
        for (int ks = 0; ks < 16; ks += 8) {
            uint32_t af[4][4], bf[4][2];
            #pragma unroll
            for (int mt = 0; mt < 4; mt++) {
                int rb = warpM * 64 + mt * 16;
                af[mt][0] = __float_as_uint(As_h[rb + gid    ][ks + tg    ]);
                af[mt][1] = __float_as_uint(As_h[rb + gid + 8][ks + tg    ]);
                af[mt][2] = __float_as_uint(As_h[rb + gid    ][ks + tg + 4]);
                af[mt][3] = __float_as_uint(As_h[rb + gid + 8][ks + tg + 4]);
            }
            #pragma unroll
            for (int nt = 0; nt < 4; nt++) {
                int nb = warpN * 32 + nt * 8;
                bf[nt][0] = __float_as_uint(Bs_h[ks + tg    ][nb + gid]);
                bf[nt][1] = __float_as_uint(Bs_h[ks + tg + 4][nb + gid]);
            }
            #pragma unroll
            for (int mt = 0; mt < 4; mt++)
                #pragma unroll
                for (int nt = 0; nt < 4; nt++)
                    mma_tf32(acc[mt][nt], af[mt], bf[nt]);
        }
        __syncthreads();
    }

    #pragma unroll
    for (int mt = 0; mt < 4; mt++) {
        #pragma unroll
        for (int nt = 0; nt < 4; nt++) {
            int col  = colTile + warpN * 32 + nt * 8 + tg * 2;
            int row0 = rowTile + warpM * 64 + mt * 16 + gid;
            int row1 = row0 + 8;
            float2 o0 = make_float2(acc[mt][nt][0], acc[mt][nt][1]);
            float2 o1 = make_float2(acc[mt][nt][2], acc[mt][nt][3]);
            if (EPI >= 1) {
                float b0 = bias[col], b1 = bias[col + 1];
                o0.x += b0; o0.y += b1; o1.x += b0; o1.y += b1;
            }
            if (EPI == 2) {
                o0.x = gelu_exact(o0.x); o0.y = gelu_exact(o0.y);
                o1.x = gelu_exact(o1.x); o1.y = gelu_exact(o1.y);
            }
            if (EPI == 3) {
                const float* r0p = R + (size_t)row0 * Ncols + col;
                const float* r1p = R + (size_t)row1 * Ncols + col;
                o0.x += r0p[0]; o0.y += r0p[1];
                o1.x += r1p[0]; o1.y += r1p[1];
            }
            *(float2*)(C + (size_t)row0 * Ncols + col) = o0;
            *(float2*)(C + (size_t)row1 * Ncols + col) = o1;
        }
    }
}

// ---------------- bf16x3 GEMM (fp32-accurate via hi/lo split) ---------------
// C = A @ B with A,B split into bf16 hi+lo; products hi*hi + hi*lo + lo*hi.
// BM=128, BN=128, BK=16, 256 threads, m16n8k16 bf16 HMMA.
// Smem tiles store packed bf16x2 k-pairs, row stride 12 u32 (conflict-free
// fragment LDS: banks = 12*gid + tg, all distinct mod 32).
template <int EPI>
__global__ __launch_bounds__(256) void gemm_bf16x3(
    const float* __restrict__ A, const float* __restrict__ Bm,
    const float* __restrict__ bias, const float* __restrict__ R,
    float* __restrict__ C, int M, int Ncols, int K)
{
    __shared__ uint32_t Ah[128][12], Al[128][12];
    __shared__ uint32_t Bh[128][12], Bl[128][12];

    int tid = threadIdx.x, wid = tid >> 5, lane = tid & 31;
    int gid = lane >> 2, tg = lane & 3;
    int warpM = wid & 1, warpN = wid >> 1;
    int rowTile = blockIdx.y * 128, colTile = blockIdx.x * 128;

    float acc[4][4][4] = {};

    for (int k0 = 0; k0 < K; k0 += 16) {
        // ---- A tile 128x16: each thread 2 float4 (4 consecutive k) ----
        #pragma unroll
        for (int i = 0; i < 2; i++) {
            int idx = tid + i * 256;
            int r = idx >> 2, c4 = (idx & 3) * 4;     // k offset 0,4,8,12
            float4 a = *(const float4*)(A + (size_t)(rowTile + r) * K + k0 + c4);
            float hx, lx, hy, ly, hz, lz, hw, lw;
            split_bf16(a.x, hx, lx); split_bf16(a.y, hy, ly);
            split_bf16(a.z, hz, lz); split_bf16(a.w, hw, lw);
            int p = c4 >> 1;                          // k-pair index 0,2,4,6
            Ah[r][p]     = pack2_bf16(hx, hy);
            Ah[r][p + 1] = pack2_bf16(hz, hw);
            Al[r][p]     = pack2_bf16(lx, ly);
            Al[r][p + 1] = pack2_bf16(lz, lw);
        }
        // ---- B tile 16x128 -> [col][kpair]: thread = (kpair, 4 cols) ----
        {
            int k2 = tid & 7;                          // k-pair 0..7
            int n4 = (tid >> 3) * 4;                   // col 0..124
            const float* bp = Bm + (size_t)(k0 + 2 * k2) * Ncols + colTile + n4;
            float4 b0 = *(const float4*)bp;
            float4 b1 = *(const float4*)(bp + Ncols);
            float h0, l0, h1, l1;
            split_bf16(b0.x, h0, l0); split_bf16(b1.x, h1, l1);
            Bh[n4 + 0][k2] = pack2_bf16(h0, h1);  Bl[n4 + 0][k2] = pack2_bf16(l0, l1);
            split_bf16(b0.y, h0, l0); split_bf16(b1.y, h1, l1);
            Bh[n4 + 1][k2] = pack2_bf16(h0, h1);  Bl[n4 + 1][k2] = pack2_bf16(l0, l1);
            split_bf16(b0.z, h0, l0); split_bf16(b1.z, h1, l1);
            Bh[n4 + 2][k2] = pack2_bf16(h0, h1);  Bl[n4 + 2][k2] = pack2_bf16(l0, l1);
            split_bf16(b0.w, h0, l0); split_bf16(b1.w, h1, l1);
            Bh[n4 + 3][k2] = pack2_bf16(h0, h1);  Bl[n4 + 3][k2] = pack2_bf16(l0, l1);
        }
        __syncthreads();

        uint32_t ah[4][4], al[4][4], bh[4][2], bl[4][2];
        #pragma unroll
        for (int mt = 0; mt < 4; mt++) {
            int rb = warpM * 64 + mt * 16;
            ah[mt][0] = Ah[rb + gid    ][tg    ];
            ah[mt][1] = Ah[rb + gid + 8][tg    ];
            ah[mt][2] = Ah[rb + gid    ][tg + 4];
            ah[mt][3] = Ah[rb + gid + 8][tg + 4];
            al[mt][0] = Al[rb + gid    ][tg    ];
            al[mt][1] = Al[rb + gid + 8][tg    ];
            al[mt][2] = Al[rb + gid    ][tg + 4];
            al[mt][3] = Al[rb + gid + 8][tg + 4];
        }
        #pragma unroll
        for (int nt = 0; nt < 4; nt++) {
            int nb = warpN * 32 + nt * 8;
            bh[nt][0] = Bh[nb + gid][tg    ];
            bh[nt][1] = Bh[nb + gid][tg + 4];
            bl[nt][0] = Bl[nb + gid][tg    ];
            bl[nt][1] = Bl[nb + gid][tg + 4];
        }
        #pragma unroll
        for (int mt = 0; mt < 4; mt++)
            #pragma unroll
            for (int nt = 0; nt < 4; nt++) {
                mma_bf16(acc[mt][nt], ah[mt], bh[nt]);
                mma_bf16(acc[mt][nt], ah[mt], bl[nt]);
                mma_bf16(acc[mt][nt], al[mt], bh[nt]);
            }
        __syncthreads();
    }

    #pragma unroll
    for (int mt = 0; mt < 4; mt++) {
        #pragma unroll
        for (int nt = 0; nt < 4; nt++) {
            int col  = colTile + warpN * 32 + nt * 8 + tg * 2;
            int row0 = rowTile + warpM * 64 + mt * 16 + gid;
            int row1 = row0 + 8;
            float2 o0 = make_float2(acc[mt][nt][0], acc[mt][nt][1]);
            float2 o1 = make_float2(acc[mt][nt][2], acc[mt][nt][3]);
            if (EPI >= 1) {
                float b0 = bias[col], b1 = bias[col + 1];
                o0.x += b0; o0.y += b1; o1.x += b0; o1.y += b1;
            }
            if (EPI == 2) {
                o0.x = gelu_exact(o0.x); o0.y = gelu_exact(o0.y);
                o1.x = gelu_exact(o1.x); o1.y = gelu_exact(o1.y);
            }
            if (EPI == 3) {
                const float* r0p = R + (size_t)row0 * Ncols + col;
                const float* r1p = R + (size_t)row1 * Ncols + col;
                o0.x += r0p[0]; o0.y += r0p[1];
                o1.x += r1p[0]; o1.y += r1p[1];
            }
            *(float2*)(C + (size_t)row0 * Ncols + col) = o0;
            *(float2*)(C + (size_t)row1 * Ncols + col) = o1;
        }
    }
}

// ---------------- Flash attention (tf32 MMA, online softmax) ----------------
#define FLDS 68
#define FSM_BYTES (3 * 64 * FLDS * 4)

__global__ __launch_bounds__(128, 3) void flash_tf32(
    const float* __restrict__ qp, const float* __restrict__ kp,
    const float* __restrict__ vp, float* __restrict__ att)
{
    extern __shared__ float sm_[];
    float* Ks = sm_;
    float* Vs = sm_ + 64 * FLDS;
    float* Ps = sm_ + 2 * 64 * FLDS;   // also Q staging

    int z = blockIdx.y, b = z >> 3, hh = z & 7;
    const float* Q = qp + (size_t)b * SEQ * DIMD + hh * HD;
    const float* K = kp + (size_t)b * SEQ * DIMD + hh * HD;
    const float* V = vp + (size_t)b * SEQ * DIMD + hh * HD;
    float* O = att + (size_t)b * SEQ * DIMD + hh * HD;
    int q0 = blockIdx.x * 64;

    int tid = threadIdx.x, wid = tid >> 5, lane = tid & 31;
    int gid = lane >> 2, tg = lane & 3;
    int rb = wid * 16;

    for (int idx = tid; idx < 64 * 16; idx += 128) {
        int r = idx >> 4, c4 = (idx & 15) * 4;
        float4 a = *(const float4*)(Q + (size_t)(q0 + r) * DIMD + c4);
        a.x *= 0.125f; a.y *= 0.125f; a.z *= 0.125f; a.w *= 0.125f;
        *(float4*)&Ps[r * FLDS + c4] = a;
    }
    __syncthreads();
    uint32_t qf[8][4];
    #pragma unroll
    for (int ki = 0; ki < 8; ki++) {
        int ks = ki * 8;
        qf[ki][0] = __float_as_uint(Ps[(rb + gid    ) * FLDS + ks + tg    ]);
        qf[ki][1] = __float_as_uint(Ps[(rb + gid + 8) * FLDS + ks + tg    ]);
        qf[ki][2] = __float_as_uint(Ps[(rb + gid    ) * FLDS + ks + tg + 4]);
        qf[ki][3] = __float_as_uint(Ps[(rb + gid + 8) * FLDS + ks + tg + 4]);
    }
    __syncthreads();

    float m0 = -1e30f, m1 = -1e30f, l0 = 0.0f, l1 = 0.0f;
    float o[8][4] = {};

    for (int t0 = 0; t0 < SEQ; t0 += 64) {
        for (int idx = tid; idx < 64 * 16; idx += 128) {
            int r = idx >> 4, c4 = (idx & 15) * 4;
            *(float4*)&Ks[r * FLDS + c4] =
                *(const float4*)(K + (size_t)(t0 + r) * DIMD + c4);
            *(float4*)&Vs[r * FLDS + c4] =
                *(const float4*)(V + (size_t)(t0 + r) * DIMD + c4);
        }
        __syncthreads();

        float s[8][4] = {};
        #pragma unroll
        for (int ki = 0; ki < 8; ki++) {
            int ks = ki * 8;
            #pragma unroll
            for (int nt = 0; nt < 8; nt++) {
                uint32_t bf[2];
                bf[0] = __float_as_uint(Ks[(nt * 8 + gid) * FLDS + ks + tg    ]);
                bf[1] = __float_as_uint(Ks[(nt * 8 + gid) * FLDS + ks + tg + 4]);
                mma_tf32(s[nt], qf[ki], bf);
            }
        }

        float tm0 = -1e30f, tm1 = -1e30f;
        #pragma unroll
        for (int nt = 0; nt < 8; nt++) {
            tm0 = fmaxf(tm0, fmaxf(s[nt][0], s[nt][1]));
            tm1 = fmaxf(tm1, fmaxf(s[nt][2], s[nt][3]));
        }
        tm0 = fmaxf(tm0, __shfl_xor_sync(0xffffffffu, tm0, 1));
        tm0 = fmaxf(tm0, __shfl_xor_sync(0xffffffffu, tm0, 2));
        tm1 = fmaxf(tm1, __shfl_xor_sync(0xffffffffu, tm1, 1));
        tm1 = fmaxf(tm1, __shfl_xor_sync(0xffffffffu, tm1, 2));
        float nm0 = fmaxf(m0, tm0), nm1 = fmaxf(m1, tm1);
        float r0 = __expf(m0 - nm0), r1 = __expf(m1 - nm1);
        float sum0 = 0.0f, sum1 = 0.0f;
        #pragma unroll
        for (int nt = 0; nt < 8; nt++) {
            s[nt][0] = __expf(s[nt][0] - nm0);
            s[nt][1] = __expf(s[nt][1] - nm0);
            s[nt][2] = __expf(s[nt][2] - nm1);
            s[nt][3] = __expf(s[nt][3] - nm1);
            sum0 += s[nt][0] + s[nt][1];
            sum1 += s[nt][2] + s[nt][3];
        }
        sum0 += __shfl_xor_sync(0xffffffffu, sum0, 1);
        sum0 += __shfl_xor_sync(0xffffffffu, sum0, 2);
        sum1 += __shfl_xor_sync(0xffffffffu, sum1, 1);
        sum1 += __shfl_xor_sync(0xffffffffu, sum1, 2);
        l0 = l0 * r0 + sum0;
        l1 = l1 * r1 + sum1;
        m0 = nm0; m1 = nm1;
        #pragma unroll
        for (int nt = 0; nt < 8; nt++) {
            o[nt][0] *= r0; o[nt][1] *= r0;
            o[nt][2] *= r1; o[nt][3] *= r1;
        }

        #pragma unroll
        for (int nt = 0; nt < 8; nt++) {
            *(float2*)&Ps[(rb + gid    ) * FLDS + nt * 8 + tg * 2] =
                make_float2(s[nt][0], s[nt][1]);
            *(float2*)&Ps[(rb + gid + 8) * FLDS + nt * 8 + tg * 2] =
                make_float2(s[nt][2], s[nt][3]);
        }
        __syncthreads();

        #pragma unroll
        for (int ki = 0; ki < 8; ki++) {
            int ks = ki * 8;
            uint32_t af[4];
            af[0] = __float_as_uint(Ps[(rb + gid    ) * FLDS + ks + tg    ]);
            af[1] = __float_as_uint(Ps[(rb + gid + 8) * FLDS + ks + tg    ]);
            af[2] = __float_as_uint(Ps[(rb + gid    ) * FLDS + ks + tg + 4]);
            af[3] = __float_as_uint(Ps[(rb + gid + 8) * FLDS + ks + tg + 4]);
            #pragma unroll
            for (int nt = 0; nt < 8; nt++) {
                uint32_t bf[2];
                bf[0] = __float_as_uint(Vs[(ks + tg    ) * FLDS + nt * 8 + gid]);
                bf[1] = __float_as_uint(Vs[(ks + tg + 4) * FLDS + nt * 8 + gid]);
                mma_tf32(o[nt], af, bf);
            }
        }
        __syncthreads();
    }

    float inv0 = 1.0f / l0, inv1 = 1.0f / l1;
    int row0 = q0 + rb + gid, row1 = row0 + 8;
    #pragma unroll
    for (int nt = 0; nt < 8; nt++) {
        int col = nt * 8 + tg * 2;
        *(float2*)(O + (size_t)row0 * DIMD + col) =
            make_float2(o[nt][0] * inv0, o[nt][1] * inv0);
        *(float2*)(O + (size_t)row1 * DIMD + col) =
            make_float2(o[nt][2] * inv1, o[nt][3] * inv1);
    }
}

// ---------------- launch ----------------------------------------------------
extern "C" void kernel_launch(void* const* d_in, const int* in_sizes, int n_in,
                              void* d_out, int out_size) {
    const float* x   = (const float*)d_in[0];
    const float* Wq  = (const float*)d_in[1];
    const float* Wk  = (const float*)d_in[2];
    const float* Wv  = (const float*)d_in[3];
    const float* Wo  = (const float*)d_in[4];
    const float* bo  = (const float*)d_in[5];
    const float* W1  = (const float*)d_in[6];
    const float* b1  = (const float*)d_in[7];
    const float* W2  = (const float*)d_in[8];
    const float* b2  = (const float*)d_in[9];
    const float* g1  = (const float*)d_in[10];
    const float* be1 = (const float*)d_in[11];
    const float* g2  = (const float*)d_in[12];
    const float* be2 = (const float*)d_in[13];
    float* out = (float*)d_out;

    float *h, *q, *k, *v, *att, *xm, *ff;
    cudaGetSymbolAddress((void**)&h,   g_h);
    cudaGetSymbolAddress((void**)&q,   g_q);
    cudaGetSymbolAddress((void**)&k,   g_k);
    cudaGetSymbolAddress((void**)&v,   g_v);
    cudaGetSymbolAddress((void**)&att, g_att);
    cudaGetSymbolAddress((void**)&xm,  g_xm);
    cudaGetSymbolAddress((void**)&ff,  g_ff);

    cudaFuncSetAttribute(flash_tf32,
                         cudaFuncAttributeMaxDynamicSharedMemorySize, FSM_BYTES);

    dim3 gProj(DIMD / 128, BN_TOK / 128);       // (4, 64)
    dim3 gMlp(MLPD / 128, BN_TOK / 128);        // (16, 64)

    // 1) h = LN(x; g1, be1)
    ln_kernel<<<BN_TOK, 128>>>(x, g1, be1, h);
    // 2) q, k, v projections (single-pass tf32)
    gemm_tf32<0><<<gProj, 256>>>(h, Wq, nullptr, nullptr, q, BN_TOK, DIMD, DIMD);
    gemm_tf32<0><<<gProj, 256>>>(h, Wk, nullptr, nullptr, k, BN_TOK, DIMD, DIMD);
    gemm_tf32<0><<<gProj, 256>>>(h, Wv, nullptr, nullptr, v, BN_TOK, DIMD, DIMD);
    // 3-5) fused flash attention
    flash_tf32<<<dim3(SEQ / 64, BATCH * HEADS), 128, FSM_BYTES>>>(q, k, v, att);
    // 6) xm = x + att @ Wo + bo
    gemm_tf32<3><<<gProj, 256>>>(att, Wo, bo, x, xm, BN_TOK, DIMD, DIMD);
    // 7) h = LN(xm; g2, be2)
    ln_kernel<<<BN_TOK, 128>>>(xm, g2, be2, h);
    // 8) ff = gelu(h @ W1 + b1)   (bf16x3 split)
    gemm_bf16x3<2><<<gMlp, 256>>>(h, W1, b1, nullptr, ff, BN_TOK, MLPD, DIMD);
    // 9) out = xm + ff @ W2 + b2  (bf16x3 split)
    gemm_bf16x3<3><<<gProj, 256>>>(ff, W2, b2, xm, out, BN_TOK, DIMD, MLPD);
}